// round 5
// baseline (speedup 1.0000x reference)
#include <cuda_runtime.h>
#include <mma.h>

using namespace nvcuda;

#define NROWS 4096
#define HDIM  512
#define VDIM  32000
#define SDIM  400
#define BDIM  32
#define TDIM  128
#define CDIM  620
#define OUTW  32620   // VDIM + CDIM

__device__ float g_pcopy[NROWS];
__device__ float g_rowsum[NROWS];

__device__ __forceinline__ float to_tf32(float x) {
    unsigned u;
    asm("cvt.rna.tf32.f32 %0, %1;" : "=r"(u) : "f"(x));
    return __uint_as_float(u);
}

// ---------------------------------------------------------------------------
// K1: p_copy[n] = sigmoid(hidden[n] . Wc + bc)   (one warp per row)
// ---------------------------------------------------------------------------
__global__ void pcopy_kernel(const float* __restrict__ hidden,
                             const float* __restrict__ Wc,
                             const float* __restrict__ bc) {
    int warp = (blockIdx.x * blockDim.x + threadIdx.x) >> 5;
    int lane = threadIdx.x & 31;
    if (warp >= NROWS) return;
    const float* h = hidden + (size_t)warp * HDIM;
    float s = 0.f;
    #pragma unroll
    for (int k = lane; k < HDIM; k += 32) s += h[k] * Wc[k];
    #pragma unroll
    for (int o = 16; o > 0; o >>= 1) s += __shfl_down_sync(0xffffffffu, s, o);
    if (lane == 0) g_pcopy[warp] = 1.f / (1.f + __expf(-(s + bc[0])));
}

// ---------------------------------------------------------------------------
// K2: logits = hidden @ W^T   (TF32 wmma, 128x128x32 tiles, raw logits to out)
// ---------------------------------------------------------------------------
#define BM 128
#define BN 128
#define BK 32

__global__ __launch_bounds__(256)
void gemm_kernel(const float* __restrict__ hidden,
                 const float* __restrict__ W,
                 float* __restrict__ out) {
    __shared__ __align__(32) float As[BM * BK];
    __shared__ __align__(32) float Bs[BN * BK];

    const int tid = threadIdx.x;
    const int n0 = blockIdx.x * BN;
    const int m0 = blockIdx.y * BM;

    const int wid  = tid >> 5;
    const int lane = tid & 31;
    const int wm = wid & 3;     // 4 warps along M -> 32 rows each
    const int wn = wid >> 2;    // 2 warps along N -> 64 cols each

    wmma::fragment<wmma::accumulator, 16, 16, 8, float> cf[2][4];
    #pragma unroll
    for (int i = 0; i < 2; i++)
        #pragma unroll
        for (int j = 0; j < 4; j++)
            wmma::fill_fragment(cf[i][j], 0.f);

    // register-prefetch buffers (4 float4 per thread per operand)
    float4 av[4], bv[4];

    #pragma unroll
    for (int q = 0; q < 4; q++) {
        int t = tid + q * 256;
        int r = t >> 3, c4 = (t & 7) << 2;
        av[q] = *reinterpret_cast<const float4*>(&hidden[(size_t)(m0 + r) * HDIM + c4]);
        bv[q] = *reinterpret_cast<const float4*>(&W[(size_t)(n0 + r) * HDIM + c4]);
    }

    for (int k0 = 0; k0 < HDIM; k0 += BK) {
        __syncthreads();
        #pragma unroll
        for (int q = 0; q < 4; q++) {
            int t = tid + q * 256;
            int r = t >> 3, c4 = (t & 7) << 2;
            float* da = &As[r * BK + c4];
            da[0] = to_tf32(av[q].x); da[1] = to_tf32(av[q].y);
            da[2] = to_tf32(av[q].z); da[3] = to_tf32(av[q].w);
            float* db = &Bs[r * BK + c4];
            db[0] = to_tf32(bv[q].x); db[1] = to_tf32(bv[q].y);
            db[2] = to_tf32(bv[q].z); db[3] = to_tf32(bv[q].w);
        }
        __syncthreads();

        if (k0 + BK < HDIM) {
            #pragma unroll
            for (int q = 0; q < 4; q++) {
                int t = tid + q * 256;
                int r = t >> 3, c4 = (t & 7) << 2;
                av[q] = *reinterpret_cast<const float4*>(&hidden[(size_t)(m0 + r) * HDIM + k0 + BK + c4]);
                bv[q] = *reinterpret_cast<const float4*>(&W[(size_t)(n0 + r) * HDIM + k0 + BK + c4]);
            }
        }

        #pragma unroll
        for (int kk = 0; kk < BK; kk += 8) {
            wmma::fragment<wmma::matrix_a, 16, 16, 8, wmma::precision::tf32, wmma::row_major> af[2];
            wmma::fragment<wmma::matrix_b, 16, 16, 8, wmma::precision::tf32, wmma::col_major> bf[4];
            #pragma unroll
            for (int i = 0; i < 2; i++)
                wmma::load_matrix_sync(af[i], &As[(wm * 32 + i * 16) * BK + kk], BK);
            #pragma unroll
            for (int j = 0; j < 4; j++)
                wmma::load_matrix_sync(bf[j], &Bs[(wn * 64 + j * 16) * BK + kk], BK);
            #pragma unroll
            for (int i = 0; i < 2; i++)
                #pragma unroll
                for (int j = 0; j < 4; j++)
                    wmma::mma_sync(cf[i][j], af[i], bf[j], cf[i][j]);
        }
    }

    // epilogue: stage each 16x16 fragment through per-warp smem, scalar stores
    // (avoids global store_matrix_sync alignment constraints: OUTW rows are
    // only 16B-aligned)
    __syncthreads();
    float* scratch = &As[wid * 256];
    #pragma unroll
    for (int i = 0; i < 2; i++) {
        #pragma unroll
        for (int j = 0; j < 4; j++) {
            wmma::store_matrix_sync(scratch, cf[i][j], 16, wmma::mem_row_major);
            __syncwarp();
            int row0 = m0 + wm * 32 + i * 16;
            int col0 = n0 + wn * 64 + j * 16;
            #pragma unroll
            for (int k = 0; k < 8; k++) {
                int idx = lane + 32 * k;
                int r = idx >> 4, c = idx & 15;
                out[(size_t)(row0 + r) * OUTW + col0 + c] = scratch[idx];
            }
            __syncwarp();
        }
    }
}

// ---------------------------------------------------------------------------
// K3: g_rowsum[n] = sum_j exp(logit[n,j] + b[j])   (no max needed: |logit|<~3)
// ---------------------------------------------------------------------------
__global__ void rowsum_kernel(const float* __restrict__ out,
                              const float* __restrict__ bias) {
    int n = blockIdx.x;
    const float4* row = reinterpret_cast<const float4*>(out + (size_t)n * OUTW);
    const float4* bs  = reinterpret_cast<const float4*>(bias);
    float s = 0.f;
    for (int i = threadIdx.x; i < VDIM / 4; i += 256) {
        float4 l = row[i];
        float4 bb = bs[i];
        s += __expf(l.x + bb.x) + __expf(l.y + bb.y)
           + __expf(l.z + bb.z) + __expf(l.w + bb.w);
    }
    __shared__ float red[8];
    #pragma unroll
    for (int o = 16; o > 0; o >>= 1) s += __shfl_down_sync(0xffffffffu, s, o);
    if ((threadIdx.x & 31) == 0) red[threadIdx.x >> 5] = s;
    __syncthreads();
    if (threadIdx.x < 8) {
        s = red[threadIdx.x];
        #pragma unroll
        for (int o = 4; o > 0; o >>= 1) s += __shfl_down_sync(0xffu, s, o);
        if (threadIdx.x == 0) g_rowsum[n] = s;
    }
}

// ---------------------------------------------------------------------------
// K4: out[n,j] = exp(logit + b[j]) * (1 - p_copy[n]) / rowsum[n]
// ---------------------------------------------------------------------------
__global__ void scale_kernel(float* __restrict__ out,
                             const float* __restrict__ bias) {
    int n = blockIdx.x;
    float sc = (1.f - g_pcopy[n]) / g_rowsum[n];
    float4* row = reinterpret_cast<float4*>(out + (size_t)n * OUTW);
    const float4* bs = reinterpret_cast<const float4*>(bias);
    for (int i = threadIdx.x; i < VDIM / 4; i += 256) {
        float4 l = row[i];
        float4 bb = bs[i];
        l.x = __expf(l.x + bb.x) * sc;
        l.y = __expf(l.y + bb.y) * sc;
        l.z = __expf(l.z + bb.z) * sc;
        l.w = __expf(l.w + bb.w) * sc;
        row[i] = l;
    }
}

// ---------------------------------------------------------------------------
// K5: out[n, V+c] = p_copy[n] * sum_s attn[n,s] * src_map[s,b,c],  n = t*B + b
//     CTA = (t-tile of 16, b); thread = c; attn tile staged in smem.
// ---------------------------------------------------------------------------
__global__ void copyext_kernel(const float* __restrict__ attn,
                               const float* __restrict__ srcmap,
                               float* __restrict__ out) {
    __shared__ float a_s[16][SDIM];
    int b  = blockIdx.x & 31;
    int t0 = (blockIdx.x >> 5) << 4;

    for (int i = threadIdx.x; i < 16 * SDIM; i += blockDim.x) {
        int r = i / SDIM, s = i - r * SDIM;
        a_s[r][s] = attn[(size_t)((t0 + r) * BDIM + b) * SDIM + s];
    }
    __syncthreads();

    int c = threadIdx.x;
    if (c < CDIM) {
        float acc[16];
        #pragma unroll
        for (int r = 0; r < 16; r++) acc[r] = 0.f;
        #pragma unroll 4
        for (int s = 0; s < SDIM; s++) {
            float sv = srcmap[(size_t)(s * BDIM + b) * CDIM + c];
            #pragma unroll
            for (int r = 0; r < 16; r++) acc[r] += a_s[r][s] * sv;
        }
        #pragma unroll
        for (int r = 0; r < 16; r++) {
            int n = (t0 + r) * BDIM + b;
            out[(size_t)n * OUTW + VDIM + c] = acc[r] * g_pcopy[n];
        }
    }
}

// ---------------------------------------------------------------------------
extern "C" void kernel_launch(void* const* d_in, const int* in_sizes, int n_in,
                              void* d_out, int out_size) {
    const float* hidden = (const float*)d_in[0];   // (4096, 512)
    const float* attn   = (const float*)d_in[1];   // (4096, 400)
    const float* W      = (const float*)d_in[2];   // (32000, 512)
    const float* bias   = (const float*)d_in[3];   // (32000,)
    const float* Wc     = (const float*)d_in[4];   // (1, 512)
    const float* bc     = (const float*)d_in[5];   // (1,)
    const float* srcmap = (const float*)d_in[6];   // (400, 32, 620)
    float* out = (float*)d_out;                    // (4096, 32620)

    pcopy_kernel<<<NROWS / 8, 256>>>(hidden, Wc, bc);

    dim3 g2(VDIM / BN, NROWS / BM);                // (250, 32)
    gemm_kernel<<<g2, 256>>>(hidden, W, out);

    rowsum_kernel<<<NROWS, 256>>>(out, bias);
    scale_kernel<<<NROWS, 256>>>(out, bias);

    copyext_kernel<<<(TDIM / 16) * BDIM, 640>>>(attn, srcmap, out);
}

// round 7
// speedup vs baseline: 3.3697x; 3.3697x over previous
#include <cuda_runtime.h>
#include <cstdint>

#define NROWS 4096
#define HDIM  512
#define VDIM  32000
#define SDIM  400
#define BDIM  32
#define CDIM  620
#define OUTW  32620          // VDIM + CDIM
#define BM    128
#define BN    128
#define BK    32
#define NSTAGE (HDIM / BK)   // 16
#define NTILES (VDIM / BN)   // 250
#define SSTRIDE 36           // padded floats per smem row (conflict-free frags)
#define TILEF  (BM * SSTRIDE)        // 4608 floats per operand tile
#define STAGEF (2 * TILEF)           // 9216 floats per stage
#define DYNSMEM (3 * STAGEF * 4)     // 110592 bytes

__device__ float g_pcopy[NROWS];
__device__ float g_partial[NROWS * NTILES];

// ---------------------------------------------------------------------------
__device__ __forceinline__ uint32_t smem_u32(const void* p) {
    return (uint32_t)__cvta_generic_to_shared(p);
}
__device__ __forceinline__ void cp_async16(uint32_t dst, const void* src) {
    asm volatile("cp.async.cg.shared.global [%0], [%1], 16;\n" :: "r"(dst), "l"(src));
}
__device__ __forceinline__ void cp_commit() { asm volatile("cp.async.commit_group;\n"); }
template<int N> __device__ __forceinline__ void cp_wait() {
    asm volatile("cp.async.wait_group %0;\n" :: "n"(N));
}

__device__ __forceinline__ void mma_tf32(float c[4], uint32_t a0, uint32_t a1,
                                         uint32_t a2, uint32_t a3,
                                         uint32_t b0, uint32_t b1) {
    asm volatile(
        "mma.sync.aligned.m16n8k8.row.col.f32.tf32.tf32.f32 "
        "{%0,%1,%2,%3}, {%4,%5,%6,%7}, {%8,%9}, {%0,%1,%2,%3};"
        : "+f"(c[0]), "+f"(c[1]), "+f"(c[2]), "+f"(c[3])
        : "r"(a0), "r"(a1), "r"(a2), "r"(a3), "r"(b0), "r"(b1));
}

// ---------------------------------------------------------------------------
// K1: p_copy[n] = sigmoid(hidden[n] . Wc + bc)
// ---------------------------------------------------------------------------
__global__ void pcopy_kernel(const float* __restrict__ hidden,
                             const float* __restrict__ Wc,
                             const float* __restrict__ bc) {
    int warp = (blockIdx.x * blockDim.x + threadIdx.x) >> 5;
    int lane = threadIdx.x & 31;
    if (warp >= NROWS) return;
    const float* h = hidden + (size_t)warp * HDIM;
    float s = 0.f;
    #pragma unroll
    for (int k = lane; k < HDIM; k += 32) s += h[k] * Wc[k];
    #pragma unroll
    for (int o = 16; o > 0; o >>= 1) s += __shfl_down_sync(0xffffffffu, s, o);
    if (lane == 0) g_pcopy[warp] = 1.f / (1.f + __expf(-(s + bc[0])));
}

// ---------------------------------------------------------------------------
// K2: TF32 mma.sync GEMM 128x128x512, 3-stage cp.async, fused exp epilogue.
//     Writes exp(logit+bias) to out[:, :V] and per-(row, n-tile) exp-sums.
// ---------------------------------------------------------------------------
__device__ __forceinline__ void load_stage(const float* __restrict__ hidden,
                                           const float* __restrict__ W,
                                           int m0, int n0, int s,
                                           uint32_t aAddr, uint32_t bAddr, int tid) {
    const int k0 = s * BK;
    #pragma unroll
    for (int q = 0; q < 4; q++) {
        int f = tid + q * 256;
        int r = f >> 3, c4 = f & 7;
        uint32_t so = (uint32_t)(r * SSTRIDE + c4 * 4) * 4u;
        cp_async16(aAddr + so, hidden + (size_t)(m0 + r) * HDIM + k0 + c4 * 4);
        cp_async16(bAddr + so, W + (size_t)(n0 + r) * HDIM + k0 + c4 * 4);
    }
}

__global__ __launch_bounds__(256, 2)
void gemm_kernel(const float* __restrict__ hidden,
                 const float* __restrict__ W,
                 const float* __restrict__ bias,
                 float* __restrict__ out) {
    extern __shared__ __align__(16) float dyn[];
    __shared__ float bias_s[BN];
    __shared__ float rs_s[4][BM];

    const int tid = threadIdx.x;
    const int m0 = blockIdx.x * BM;
    const int n0 = blockIdx.y * BN;
    const int wid = tid >> 5, lane = tid & 31;
    const int wm = wid & 1;         // 2 warps along M (64 rows each)
    const int wn = wid >> 1;        // 4 warps along N (32 cols each)
    const int g = lane >> 2, t = lane & 3;

    if (tid < BN) bias_s[tid] = bias[n0 + tid];

    float c[4][4][4];
    #pragma unroll
    for (int mf = 0; mf < 4; mf++)
        #pragma unroll
        for (int nf = 0; nf < 4; nf++)
            #pragma unroll
            for (int i = 0; i < 4; i++) c[mf][nf][i] = 0.f;

    const uint32_t stAddr[3] = { smem_u32(dyn),
                                 smem_u32(dyn + STAGEF),
                                 smem_u32(dyn + 2 * STAGEF) };

    load_stage(hidden, W, m0, n0, 0, stAddr[0], stAddr[0] + TILEF * 4, tid); cp_commit();
    load_stage(hidden, W, m0, n0, 1, stAddr[1], stAddr[1] + TILEF * 4, tid); cp_commit();

    #pragma unroll 1
    for (int s = 0; s < NSTAGE; s++) {
        const int p = s % 3;
        if (s + 1 < NSTAGE) cp_wait<1>(); else cp_wait<0>();
        __syncthreads();

        const uint32_t* Asb = (const uint32_t*)(dyn + p * STAGEF)
                              + (wm * 64 + g) * SSTRIDE + t;
        const uint32_t* Bsb = (const uint32_t*)(dyn + p * STAGEF + TILEF)
                              + (wn * 32 + g) * SSTRIDE + t;

        #pragma unroll
        for (int kk = 0; kk < BK; kk += 8) {
            uint32_t a[4][4], b[4][2];
            #pragma unroll
            for (int mf = 0; mf < 4; mf++) {
                const uint32_t* pa = Asb + mf * 16 * SSTRIDE + kk;
                a[mf][0] = pa[0];
                a[mf][1] = pa[8 * SSTRIDE];
                a[mf][2] = pa[4];
                a[mf][3] = pa[8 * SSTRIDE + 4];
            }
            #pragma unroll
            for (int nf = 0; nf < 4; nf++) {
                const uint32_t* pb = Bsb + nf * 8 * SSTRIDE + kk;
                b[nf][0] = pb[0];
                b[nf][1] = pb[4];
            }
            #pragma unroll
            for (int mf = 0; mf < 4; mf++)
                #pragma unroll
                for (int nf = 0; nf < 4; nf++)
                    mma_tf32(c[mf][nf], a[mf][0], a[mf][1], a[mf][2], a[mf][3],
                             b[nf][0], b[nf][1]);
        }

        if (s + 2 < NSTAGE) {
            const int q = (s + 2) % 3;
            load_stage(hidden, W, m0, n0, s + 2, stAddr[q], stAddr[q] + TILEF * 4, tid);
            cp_commit();
        }
    }
    __syncthreads();

    // ---- epilogue: exp(+bias), row-sum partials, transposed coalesced stores
    float rs[4][2];
    #pragma unroll
    for (int mf = 0; mf < 4; mf++) { rs[mf][0] = 0.f; rs[mf][1] = 0.f; }

    #pragma unroll
    for (int mf = 0; mf < 4; mf++)
        #pragma unroll
        for (int nf = 0; nf < 4; nf++)
            #pragma unroll
            for (int i = 0; i < 4; i++) {
                int col = wn * 32 + nf * 8 + 2 * t + (i & 1);
                float e = __expf(c[mf][nf][i] + bias_s[col]);
                c[mf][nf][i] = e;
                rs[mf][i >> 1] += e;
            }

    #pragma unroll
    for (int mf = 0; mf < 4; mf++)
        #pragma unroll
        for (int h = 0; h < 2; h++) {
            float v = rs[mf][h];
            v += __shfl_xor_sync(0xffffffffu, v, 1);
            v += __shfl_xor_sync(0xffffffffu, v, 2);
            if (t == 0) rs_s[wn][wm * 64 + mf * 16 + g + h * 8] = v;
        }
    __syncthreads();
    if (tid < BM) {
        float pr = rs_s[0][tid] + rs_s[1][tid] + rs_s[2][tid] + rs_s[3][tid];
        g_partial[(size_t)(m0 + tid) * NTILES + blockIdx.y] = pr;
    }

    // 4 chunks of 32 cols: STS (conflict-free, stride 132) then float4 STG
    #pragma unroll 1
    for (int ch = 0; ch < 4; ch++) {
        if (wn == ch) {
            #pragma unroll
            for (int mf = 0; mf < 4; mf++)
                #pragma unroll
                for (int nf = 0; nf < 4; nf++)
                    #pragma unroll
                    for (int i = 0; i < 4; i++) {
                        int row = wm * 64 + mf * 16 + g + (i >> 1) * 8;
                        int col = nf * 8 + 2 * t + (i & 1);
                        dyn[col * 132 + row] = c[mf][nf][i];
                    }
        }
        __syncthreads();
        #pragma unroll
        for (int k = 0; k < 4; k++) {
            int f = tid + k * 256;
            int row = f >> 3, cg = f & 7;
            float4 v4;
            v4.x = dyn[(cg * 4 + 0) * 132 + row];
            v4.y = dyn[(cg * 4 + 1) * 132 + row];
            v4.z = dyn[(cg * 4 + 2) * 132 + row];
            v4.w = dyn[(cg * 4 + 3) * 132 + row];
            *reinterpret_cast<float4*>(
                &out[(size_t)(m0 + row) * OUTW + n0 + ch * 32 + cg * 4]) = v4;
        }
        __syncthreads();
    }
}

// ---------------------------------------------------------------------------
// K3: per-row reduce 250 partials (deterministic), scale V-range of out
// ---------------------------------------------------------------------------
__global__ void scale_kernel(float* __restrict__ out) {
    const int n = blockIdx.x;
    const int tid = threadIdx.x;
    __shared__ float red[256];
    red[tid] = (tid < NTILES) ? g_partial[(size_t)n * NTILES + tid] : 0.f;
    __syncthreads();
    #pragma unroll
    for (int o = 128; o > 0; o >>= 1) {
        if (tid < o) red[tid] += red[tid + o];
        __syncthreads();
    }
    const float sc = (1.f - g_pcopy[n]) / red[0];
    float4* row = reinterpret_cast<float4*>(out + (size_t)n * OUTW);
    for (int i = tid; i < VDIM / 4; i += 256) {
        float4 x = row[i];
        x.x *= sc; x.y *= sc; x.z *= sc; x.w *= sc;
        row[i] = x;
    }
}

// ---------------------------------------------------------------------------
// K4: out[n, V+c] = p_copy[n] * sum_s attn[n,s] * src_map[s,b,c],  n = t*B + b
// ---------------------------------------------------------------------------
__global__ void copyext_kernel(const float* __restrict__ attn,
                               const float* __restrict__ srcmap,
                               float* __restrict__ out) {
    __shared__ float a_s[16][SDIM];
    int b  = blockIdx.x & 31;
    int t0 = (blockIdx.x >> 5) << 4;

    for (int i = threadIdx.x; i < 16 * SDIM; i += blockDim.x) {
        int r = i / SDIM, s = i - r * SDIM;
        a_s[r][s] = attn[(size_t)((t0 + r) * BDIM + b) * SDIM + s];
    }
    __syncthreads();

    int c = threadIdx.x;
    if (c < CDIM) {
        float acc[16];
        #pragma unroll
        for (int r = 0; r < 16; r++) acc[r] = 0.f;
        #pragma unroll 4
        for (int s = 0; s < SDIM; s++) {
            float sv = srcmap[(size_t)(s * BDIM + b) * CDIM + c];
            #pragma unroll
            for (int r = 0; r < 16; r++) acc[r] += a_s[r][s] * sv;
        }
        #pragma unroll
        for (int r = 0; r < 16; r++) {
            int n = (t0 + r) * BDIM + b;
            out[(size_t)n * OUTW + VDIM + c] = acc[r] * g_pcopy[n];
        }
    }
}

// ---------------------------------------------------------------------------
extern "C" void kernel_launch(void* const* d_in, const int* in_sizes, int n_in,
                              void* d_out, int out_size) {
    const float* hidden = (const float*)d_in[0];   // (4096, 512)
    const float* attn   = (const float*)d_in[1];   // (4096, 400)
    const float* W      = (const float*)d_in[2];   // (32000, 512)
    const float* bias   = (const float*)d_in[3];   // (32000,)
    const float* Wc     = (const float*)d_in[4];   // (1, 512)
    const float* bc     = (const float*)d_in[5];   // (1,)
    const float* srcmap = (const float*)d_in[6];   // (400, 32, 620)
    float* out = (float*)d_out;                    // (4096, 32620)

    cudaFuncSetAttribute(gemm_kernel,
                         cudaFuncAttributeMaxDynamicSharedMemorySize, DYNSMEM);

    pcopy_kernel<<<NROWS / 8, 256>>>(hidden, Wc, bc);

    dim3 g2(NROWS / BM, NTILES);                   // (32, 250): M fast -> B reuse
    gemm_kernel<<<g2, 256, DYNSMEM>>>(hidden, W, bias, out);

    scale_kernel<<<NROWS, 256>>>(out);

    copyext_kernel<<<(NROWS / BDIM / 16) * BDIM, 640>>>(attn, srcmap, out);
}